// round 8
// baseline (speedup 1.0000x reference)
#include <cuda_runtime.h>
#include <cuda_fp16.h>
#include <cstdint>

// Problem constants: N=100000, S=8, B=4, F=128, O=64, E=3.2M
#define MAXN 100000
#define MAXE 3300000
#define FDIM 128
#define ODIM 64
#define NBAS 4
#define NREL 8

// Scratch (__device__ globals; no runtime alloc allowed)
__device__ __half g_FWh[(size_t)NREL * MAXN * ODIM];  // [8, N, 64] fp16 (102.4 MB)
__device__ __half g_Wh[NREL * ODIM * FDIM];           // [8][n=64][k=128] fp16
__device__ int    g_cnt[MAXN];                        // per-row degree
__device__ int    g_off[MAXN + 1];                    // CSR offsets
__device__ int    g_pos[MAXN];                        // scatter cursors
__device__ uint2  g_pairs[MAXE];                      // (col, val-bits) sorted by row

// ---------------------------------------------------------------------------
__device__ __forceinline__ void mma_f16(float* d, uint32_t a0, uint32_t a1, uint32_t a2,
                                        uint32_t a3, uint32_t b0, uint32_t b1) {
    asm volatile(
        "mma.sync.aligned.m16n8k16.row.col.f32.f16.f16.f32 "
        "{%0,%1,%2,%3}, {%4,%5,%6,%7}, {%8,%9}, {%0,%1,%2,%3};"
        : "+f"(d[0]), "+f"(d[1]), "+f"(d[2]), "+f"(d[3])
        : "r"(a0), "r"(a1), "r"(a2), "r"(a3), "r"(b0), "r"(b1));
}

// ---------------------------------------------------------------------------
// Kernel 0: W[s][n][k] = fp16( sum_b comp[s,b] * Bases[b][k][n] )
// ---------------------------------------------------------------------------
__global__ void wcomb_kernel(const float* __restrict__ bases, const float* __restrict__ comp) {
    int idx = blockIdx.x * blockDim.x + threadIdx.x;
    if (idx >= NREL * FDIM * ODIM) return;
    int s = idx >> 13;
    int r = idx & 8191;
    int n = r >> 7;
    int k = r & 127;
    float acc = 0.f;
    #pragma unroll
    for (int b = 0; b < NBAS; b++)
        acc += __ldg(comp + s * NBAS + b) * __ldg(bases + b * FDIM * ODIM + k * ODIM + n);
    g_Wh[idx] = __float2half_rn(acc);
}

// ---------------------------------------------------------------------------
// Kernel 1: FW[s] = X @ W[s]^T via fp16 mma (f32 accumulate), fp16 output.
// 256 thr (8 warps), tile 128x64, K=128, 87KB smem, 2 blocks/SM.
// ---------------------------------------------------------------------------
#define XS_STRIDE 136
#define WS_STRIDE 136
#define SMEM_GEMM (128 * XS_STRIDE * 2 + 64 * WS_STRIDE * 2)

__global__ void __launch_bounds__(256) gemm_fw_kernel(const float* __restrict__ X, int nN) {
    extern __shared__ __half smh[];
    __half* Xs = smh;                       // [128][136]
    __half* Ws = smh + 128 * XS_STRIDE;     // [64][136]

    const int tid = threadIdx.x;
    const int wid = tid >> 5;
    const int lane = tid & 31;
    const int g = lane >> 2;
    const int tg = lane & 3;
    const int node0 = blockIdx.x * 128;
    const int wrow = wid * 16;

    {
        const float4* X4 = (const float4*)X;
        #pragma unroll 4
        for (int i = tid; i < 4096; i += 256) {
            int row = i >> 5, q = i & 31;
            int gn = node0 + row;
            float4 v = (gn < nN) ? X4[(size_t)gn * 32 + q] : make_float4(0.f, 0.f, 0.f, 0.f);
            __half2 h0 = __floats2half2_rn(v.x, v.y);
            __half2 h1 = __floats2half2_rn(v.z, v.w);
            uint2 packed = make_uint2(*(uint32_t*)&h0, *(uint32_t*)&h1);
            *(uint2*)(Xs + row * XS_STRIDE + q * 4) = packed;
        }
    }

    for (int s = 0; s < NREL; s++) {
        __syncthreads();
        {
            const uint4* src = (const uint4*)(g_Wh + s * ODIM * FDIM);
            #pragma unroll
            for (int i = tid; i < 1024; i += 256) {
                int n = i >> 4, q = i & 15;
                *(uint4*)(Ws + n * WS_STRIDE + q * 8) = src[i];
            }
        }
        __syncthreads();

        float d[8][4];
        #pragma unroll
        for (int ni = 0; ni < 8; ni++)
            #pragma unroll
            for (int j = 0; j < 4; j++) d[ni][j] = 0.f;

        #pragma unroll
        for (int ks = 0; ks < 8; ks++) {
            const __half* ar = Xs + (wrow + g) * XS_STRIDE + ks * 16 + tg * 2;
            uint32_t a0 = *(const uint32_t*)(ar);
            uint32_t a1 = *(const uint32_t*)(ar + 8 * XS_STRIDE);
            uint32_t a2 = *(const uint32_t*)(ar + 8);
            uint32_t a3 = *(const uint32_t*)(ar + 8 * XS_STRIDE + 8);
            #pragma unroll
            for (int ni = 0; ni < 8; ni++) {
                const __half* br = Ws + (ni * 8 + g) * WS_STRIDE + ks * 16 + tg * 2;
                uint32_t b0 = *(const uint32_t*)(br);
                uint32_t b1 = *(const uint32_t*)(br + 8);
                mma_f16(d[ni], a0, a1, a2, a3, b0, b1);
            }
        }

        {
            __half* fwbase = g_FWh + (size_t)s * nN * ODIM;
            int r0 = node0 + wrow + g;
            int r1 = r0 + 8;
            #pragma unroll
            for (int ni = 0; ni < 8; ni++) {
                int c = ni * 8 + tg * 2;
                if (r0 < nN)
                    *(__half2*)(fwbase + (size_t)r0 * ODIM + c) = __floats2half2_rn(d[ni][0], d[ni][1]);
                if (r1 < nN)
                    *(__half2*)(fwbase + (size_t)r1 * ODIM + c) = __floats2half2_rn(d[ni][2], d[ni][3]);
            }
        }
    }
}

// ---------------------------------------------------------------------------
// CSR build stage A: zero counters
// ---------------------------------------------------------------------------
__global__ void zero_cnt_kernel(int nN) {
    int i = blockIdx.x * blockDim.x + threadIdx.x;
    if (i < nN) g_cnt[i] = 0;
}

// Stage B: histogram of rows
__global__ void hist_kernel(const int* __restrict__ rows, int E) {
    int e = blockIdx.x * blockDim.x + threadIdx.x;
    if (e < E) atomicAdd(&g_cnt[__ldg(rows + e)], 1);
}

// Stage C: exclusive scan (single block, 1024 threads, chunked)
__global__ void __launch_bounds__(1024) scan_kernel(int nN) {
    __shared__ int ssum[1024];
    const int tid = threadIdx.x;
    const int chunk = (nN + 1023) / 1024;
    const int start = tid * chunk;
    const int end = min(start + chunk, nN);

    int sum = 0;
    for (int i = start; i < end; i++) sum += g_cnt[i];
    ssum[tid] = sum;
    __syncthreads();

    // Hillis-Steele inclusive scan on block sums
    #pragma unroll
    for (int d = 1; d < 1024; d <<= 1) {
        int v = (tid >= d) ? ssum[tid - d] : 0;
        __syncthreads();
        ssum[tid] += v;
        __syncthreads();
    }
    int base = (tid == 0) ? 0 : ssum[tid - 1];

    for (int i = start; i < end; i++) {
        int c = g_cnt[i];
        g_off[i] = base;
        g_pos[i] = base;
        base += c;
    }
    if (tid == 1023) g_off[nN] = base;
}

// Stage D: scatter (col, val) into row-sorted order
__global__ void scatter_kernel(const int* __restrict__ rows, const int* __restrict__ cols,
                               const float* __restrict__ vals, int E) {
    int e = blockIdx.x * blockDim.x + threadIdx.x;
    if (e >= E) return;
    int r = __ldg(rows + e);
    int p = atomicAdd(&g_pos[r], 1);
    g_pairs[p] = make_uint2((uint32_t)__ldg(cols + e), __float_as_uint(__ldg(vals + e)));
}

// ---------------------------------------------------------------------------
// Kernel 2: pull-mode SpMM + fused bias + ReLU. One warp per output row.
// Per edge: broadcast 8B pair + coalesced 128B FW gather; fp32 reg accumulate.
// ---------------------------------------------------------------------------
__global__ void __launch_bounds__(256) pull_kernel(float* __restrict__ out,
                                                   const float* __restrict__ bias, int nN) {
    int row = blockIdx.x * 8 + (threadIdx.x >> 5);
    if (row >= nN) return;
    int lane = threadIdx.x & 31;

    int i = g_off[row];
    const int end = g_off[row + 1];

    float a0 = 0.f, a1 = 0.f;

    // unroll-by-2 with front-batched independent loads
    for (; i + 2 <= end; i += 2) {
        uint2 p0 = __ldg(&g_pairs[i]);
        uint2 p1 = __ldg(&g_pairs[i + 1]);
        uint32_t h0 = *(const uint32_t*)(g_FWh + (size_t)p0.x * ODIM + lane * 2);
        uint32_t h1 = *(const uint32_t*)(g_FWh + (size_t)p1.x * ODIM + lane * 2);
        float v0 = __uint_as_float(p0.y);
        float v1 = __uint_as_float(p1.y);
        float2 f0 = __half22float2(*(__half2*)&h0);
        float2 f1 = __half22float2(*(__half2*)&h1);
        a0 = fmaf(v0, f0.x, a0); a1 = fmaf(v0, f0.y, a1);
        a0 = fmaf(v1, f1.x, a0); a1 = fmaf(v1, f1.y, a1);
    }
    if (i < end) {
        uint2 p0 = __ldg(&g_pairs[i]);
        uint32_t h0 = *(const uint32_t*)(g_FWh + (size_t)p0.x * ODIM + lane * 2);
        float v0 = __uint_as_float(p0.y);
        float2 f0 = __half22float2(*(__half2*)&h0);
        a0 = fmaf(v0, f0.x, a0); a1 = fmaf(v0, f0.y, a1);
    }

    float2 bb = __ldg((const float2*)bias + lane);
    float2 o;
    o.x = fmaxf(a0 + bb.x, 0.f);
    o.y = fmaxf(a1 + bb.y, 0.f);
    *(float2*)(out + (size_t)row * ODIM + lane * 2) = o;
}

// ---------------------------------------------------------------------------
extern "C" void kernel_launch(void* const* d_in, const int* in_sizes, int n_in,
                              void* d_out, int out_size) {
    const float* X     = (const float*)d_in[0];   // [N, 128]
    const int*   rows  = (const int*)  d_in[1];   // [E]
    const int*   cols  = (const int*)  d_in[2];   // [E]
    const float* vals  = (const float*)d_in[3];   // [E]
    const float* bases = (const float*)d_in[4];   // [4, 128, 64]
    const float* comp  = (const float*)d_in[5];   // [8, 4]
    const float* bias  = (const float*)d_in[6];   // [64]
    float* out = (float*)d_out;                   // [N, 64]

    int nN = in_sizes[0] / FDIM;
    int E  = in_sizes[1];

    cudaFuncSetAttribute(gemm_fw_kernel, cudaFuncAttributeMaxDynamicSharedMemorySize, SMEM_GEMM);

    // CSR build (independent of GEMM; runs first so pull is the only consumer)
    zero_cnt_kernel<<<(nN + 255) / 256, 256>>>(nN);
    hist_kernel<<<(E + 255) / 256, 256>>>(rows, E);
    scan_kernel<<<1, 1024>>>(nN);
    scatter_kernel<<<(E + 255) / 256, 256>>>(rows, cols, vals, E);

    wcomb_kernel<<<(NREL * FDIM * ODIM + 255) / 256, 256>>>(bases, comp);

    int gblocks = (nN + 127) / 128;
    gemm_fw_kernel<<<gblocks, 256, SMEM_GEMM>>>(X, nN);

    pull_kernel<<<(nN + 7) / 8, 256>>>(out, bias, nN);
}

// round 9
// speedup vs baseline: 1.2255x; 1.2255x over previous
#include <cuda_runtime.h>
#include <cuda_fp16.h>
#include <cstdint>

// Problem constants: N=100000, S=8, B=4, F=128, O=64, E=3.2M
#define MAXN 100000
#define FDIM 128
#define ODIM 64
#define NBAS 4
#define NREL 8

// Scratch (__device__ globals; no runtime alloc allowed)
__device__ __half g_FWh[(size_t)NREL * MAXN * ODIM];  // [8, N, 64] fp16 (102.4 MB)
__device__ __half g_Wh[NREL * ODIM * FDIM];           // [8][n=64][k=128] fp16

// ---------------------------------------------------------------------------
__device__ __forceinline__ void mma_f16(float* d, uint32_t a0, uint32_t a1, uint32_t a2,
                                        uint32_t a3, uint32_t b0, uint32_t b1) {
    asm volatile(
        "mma.sync.aligned.m16n8k16.row.col.f32.f16.f16.f32 "
        "{%0,%1,%2,%3}, {%4,%5,%6,%7}, {%8,%9}, {%0,%1,%2,%3};"
        : "+f"(d[0]), "+f"(d[1]), "+f"(d[2]), "+f"(d[3])
        : "r"(a0), "r"(a1), "r"(a2), "r"(a3), "r"(b0), "r"(b1));
}

// ---------------------------------------------------------------------------
// Kernel 0: W[s][n][k] = fp16( sum_b comp[s,b] * Bases[b][k][n] )
// ---------------------------------------------------------------------------
__global__ void wcomb_kernel(const float* __restrict__ bases, const float* __restrict__ comp) {
    int idx = blockIdx.x * blockDim.x + threadIdx.x;
    if (idx >= NREL * FDIM * ODIM) return;
    int s = idx >> 13;
    int r = idx & 8191;
    int n = r >> 7;
    int k = r & 127;
    float acc = 0.f;
    #pragma unroll
    for (int b = 0; b < NBAS; b++)
        acc += __ldg(comp + s * NBAS + b) * __ldg(bases + b * FDIM * ODIM + k * ODIM + n);
    g_Wh[idx] = __float2half_rn(acc);
}

// ---------------------------------------------------------------------------
// Kernel 1: FW[s] = X @ W[s]^T via fp16 mma, STAGED coalesced epilogue.
// 256 thr (8 warps), tile 128x64, K=128.
// smem: Xs[128][136]h (69632) + Ws[64][136]h (17408) + stage[128][72]h (18432)
//       = 105472 B -> still 2 blocks/SM (limit 113.6 KB).
// Stage stride 72 halves = 36 words: STS bank (4g+tg)%32 bijective -> no conflicts.
// ---------------------------------------------------------------------------
#define XS_STRIDE 136
#define WS_STRIDE 136
#define ST_STRIDE 72                        // halves (36 words)
#define SMEM_GEMM (128 * XS_STRIDE * 2 + 64 * WS_STRIDE * 2 + 128 * ST_STRIDE * 2)

__global__ void __launch_bounds__(256) gemm_fw_kernel(const float* __restrict__ X, int nN) {
    extern __shared__ __half smh[];
    __half* Xs = smh;                               // [128][136]
    __half* Ws = smh + 128 * XS_STRIDE;             // [64][136]
    __half* St = Ws + 64 * WS_STRIDE;               // [128][72]

    const int tid = threadIdx.x;
    const int wid = tid >> 5;
    const int lane = tid & 31;
    const int g = lane >> 2;
    const int tg = lane & 3;
    const int node0 = blockIdx.x * 128;
    const int wrow = wid * 16;

    // Load X tile [128 x 128] fp32 -> fp16 smem
    {
        const float4* X4 = (const float4*)X;
        #pragma unroll 4
        for (int i = tid; i < 4096; i += 256) {
            int row = i >> 5, q = i & 31;
            int gn = node0 + row;
            float4 v = (gn < nN) ? X4[(size_t)gn * 32 + q] : make_float4(0.f, 0.f, 0.f, 0.f);
            __half2 h0 = __floats2half2_rn(v.x, v.y);
            __half2 h1 = __floats2half2_rn(v.z, v.w);
            uint2 packed = make_uint2(*(uint32_t*)&h0, *(uint32_t*)&h1);
            *(uint2*)(Xs + row * XS_STRIDE + q * 4) = packed;
        }
    }

    for (int s = 0; s < NREL; s++) {
        __syncthreads();   // prior iter's Ws/St consumption done (publishes Xs on s=0)
        // Load W_s [64][128] fp16 (1024 uint4)
        {
            const uint4* src = (const uint4*)(g_Wh + s * ODIM * FDIM);
            #pragma unroll
            for (int i = tid; i < 1024; i += 256) {
                int n = i >> 4, q = i & 15;
                *(uint4*)(Ws + n * WS_STRIDE + q * 8) = src[i];
            }
        }
        __syncthreads();

        float d[8][4];
        #pragma unroll
        for (int ni = 0; ni < 8; ni++)
            #pragma unroll
            for (int j = 0; j < 4; j++) d[ni][j] = 0.f;

        #pragma unroll
        for (int ks = 0; ks < 8; ks++) {
            const __half* ar = Xs + (wrow + g) * XS_STRIDE + ks * 16 + tg * 2;
            uint32_t a0 = *(const uint32_t*)(ar);
            uint32_t a1 = *(const uint32_t*)(ar + 8 * XS_STRIDE);
            uint32_t a2 = *(const uint32_t*)(ar + 8);
            uint32_t a3 = *(const uint32_t*)(ar + 8 * XS_STRIDE + 8);
            #pragma unroll
            for (int ni = 0; ni < 8; ni++) {
                const __half* br = Ws + (ni * 8 + g) * WS_STRIDE + ks * 16 + tg * 2;
                uint32_t b0 = *(const uint32_t*)(br);
                uint32_t b1 = *(const uint32_t*)(br + 8);
                mma_f16(d[ni], a0, a1, a2, a3, b0, b1);
            }
        }

        // Stage to smem (conflict-free STS.32), then coalesced global flush
        {
            __half* s0 = St + (wrow + g) * ST_STRIDE;          // row wrow+g
            __half* s1 = St + (wrow + 8 + g) * ST_STRIDE;      // row wrow+g+8
            #pragma unroll
            for (int ni = 0; ni < 8; ni++) {
                int c = ni * 8 + tg * 2;
                *(__half2*)(s0 + c) = __floats2half2_rn(d[ni][0], d[ni][1]);
                *(__half2*)(s1 + c) = __floats2half2_rn(d[ni][2], d[ni][3]);
            }
        }
        __syncthreads();
        {
            __half* fwbase = g_FWh + (size_t)s * nN * ODIM;
            #pragma unroll
            for (int i = tid; i < 1024; i += 256) {
                int r = i >> 3, q = i & 7;                     // row, 16B-group
                int gn = node0 + r;
                if (gn < nN) {
                    uint4 v = *(const uint4*)(St + r * ST_STRIDE + q * 8);
                    *(uint4*)(fwbase + (size_t)gn * ODIM + q * 8) = v;
                }
            }
        }
    }
}

// ---------------------------------------------------------------------------
// Kernel 2: SpMM scatter: out[rows[e]] += vals[e] * FW[cols[e]] (fp16 gather)
// 8 threads per edge: 16B load each, 2x red.v4.f32  (gather-bound; atomics free)
// ---------------------------------------------------------------------------
__global__ void spmm_kernel(const int* __restrict__ rows, const int* __restrict__ cols,
                            const float* __restrict__ vals, float* __restrict__ out, int E) {
    int t = blockIdx.x * blockDim.x + threadIdx.x;
    int e = t >> 3;
    if (e >= E) return;
    int l = t & 7;
    int c = __ldg(cols + e);
    int r = __ldg(rows + e);
    float v = __ldg(vals + e);

    const uint4* src = (const uint4*)(g_FWh + (size_t)c * ODIM) + l;
    uint4 p = *src;
    float2 f0 = __half22float2(*(__half2*)&p.x);
    float2 f1 = __half22float2(*(__half2*)&p.y);
    float2 f2 = __half22float2(*(__half2*)&p.z);
    float2 f3 = __half22float2(*(__half2*)&p.w);

    float* dst = out + (size_t)r * ODIM + l * 8;
    asm volatile("red.global.add.v4.f32 [%0], {%1,%2,%3,%4};"
                 :: "l"(dst), "f"(f0.x * v), "f"(f0.y * v), "f"(f1.x * v), "f"(f1.y * v) : "memory");
    asm volatile("red.global.add.v4.f32 [%0], {%1,%2,%3,%4};"
                 :: "l"(dst + 4), "f"(f2.x * v), "f"(f2.y * v), "f"(f3.x * v), "f"(f3.y * v) : "memory");
}

// ---------------------------------------------------------------------------
// Kernel 3: out = relu(out + bias)
// ---------------------------------------------------------------------------
__global__ void bias_relu_kernel(float* __restrict__ out, const float* __restrict__ bias, int nN) {
    int idx = blockIdx.x * blockDim.x + threadIdx.x;
    int total = nN * 16;
    if (idx >= total) return;
    float4 v = ((float4*)out)[idx];
    int og = idx & 15;
    float4 bb = __ldg((const float4*)bias + og);
    v.x = fmaxf(v.x + bb.x, 0.f);
    v.y = fmaxf(v.y + bb.y, 0.f);
    v.z = fmaxf(v.z + bb.z, 0.f);
    v.w = fmaxf(v.w + bb.w, 0.f);
    ((float4*)out)[idx] = v;
}

// ---------------------------------------------------------------------------
extern "C" void kernel_launch(void* const* d_in, const int* in_sizes, int n_in,
                              void* d_out, int out_size) {
    const float* X     = (const float*)d_in[0];   // [N, 128]
    const int*   rows  = (const int*)  d_in[1];   // [E]
    const int*   cols  = (const int*)  d_in[2];   // [E]
    const float* vals  = (const float*)d_in[3];   // [E]
    const float* bases = (const float*)d_in[4];   // [4, 128, 64]
    const float* comp  = (const float*)d_in[5];   // [8, 4]
    const float* bias  = (const float*)d_in[6];   // [64]
    float* out = (float*)d_out;                   // [N, 64]

    int nN = in_sizes[0] / FDIM;
    int E  = in_sizes[1];

    cudaFuncSetAttribute(gemm_fw_kernel, cudaFuncAttributeMaxDynamicSharedMemorySize, SMEM_GEMM);

    cudaMemsetAsync(out, 0, (size_t)nN * ODIM * sizeof(float));

    wcomb_kernel<<<(NREL * FDIM * ODIM + 255) / 256, 256>>>(bases, comp);

    int gblocks = (nN + 127) / 128;
    gemm_fw_kernel<<<gblocks, 256, SMEM_GEMM>>>(X, nN);

    long long spthreads = (long long)E * 8;
    spmm_kernel<<<(int)((spthreads + 255) / 256), 256>>>(rows, cols, vals, out, E);

    bias_relu_kernel<<<(nN * 16 + 255) / 256, 256>>>(out, bias, nN);
}

// round 10
// speedup vs baseline: 1.2407x; 1.0124x over previous
#include <cuda_runtime.h>
#include <cuda_fp16.h>
#include <cstdint>

// Problem constants: N=100000, S=8, B=4, F=128, O=64, E=3.2M
#define MAXN 100000
#define FDIM 128
#define ODIM 64
#define NBAS 4
#define NREL 8

// Scratch (__device__ globals; no runtime alloc allowed)
__device__ __half g_FWh[(size_t)NREL * MAXN * ODIM];  // [8, N, 64] fp16 (102.4 MB)
__device__ __half g_Wh[NREL * ODIM * FDIM];           // [8][n=64][k=128] fp16

// ---------------------------------------------------------------------------
__device__ __forceinline__ void mma_f16(float* d, uint32_t a0, uint32_t a1, uint32_t a2,
                                        uint32_t a3, uint32_t b0, uint32_t b1) {
    asm volatile(
        "mma.sync.aligned.m16n8k16.row.col.f32.f16.f16.f32 "
        "{%0,%1,%2,%3}, {%4,%5,%6,%7}, {%8,%9}, {%0,%1,%2,%3};"
        : "+f"(d[0]), "+f"(d[1]), "+f"(d[2]), "+f"(d[3])
        : "r"(a0), "r"(a1), "r"(a2), "r"(a3), "r"(b0), "r"(b1));
}

// ---------------------------------------------------------------------------
// Kernel 0: W[s][n][k] = fp16( sum_b comp[s,b] * Bases[b][k][n] )
// ---------------------------------------------------------------------------
__global__ void wcomb_kernel(const float* __restrict__ bases, const float* __restrict__ comp) {
    int idx = blockIdx.x * blockDim.x + threadIdx.x;
    if (idx >= NREL * FDIM * ODIM) return;
    int s = idx >> 13;
    int r = idx & 8191;
    int n = r >> 7;
    int k = r & 127;
    float acc = 0.f;
    #pragma unroll
    for (int b = 0; b < NBAS; b++)
        acc += __ldg(comp + s * NBAS + b) * __ldg(bases + b * FDIM * ODIM + k * ODIM + n);
    g_Wh[idx] = __float2half_rn(acc);
}

// ---------------------------------------------------------------------------
// Kernel 1: FW[s] = X @ W[s]^T via fp16 mma; staged epilogue;
// register-prefetched W (LDG of W_{s+1} hidden under compute of s);
// 2 syncthreads per relation (was 3).
// smem: Xs[128][136]h + Ws[64][136]h + St[128][72]h = 105472 B -> 2 blk/SM.
// ---------------------------------------------------------------------------
#define XS_STRIDE 136
#define WS_STRIDE 136
#define ST_STRIDE 72
#define SMEM_GEMM (128 * XS_STRIDE * 2 + 64 * WS_STRIDE * 2 + 128 * ST_STRIDE * 2)

__global__ void __launch_bounds__(256) gemm_fw_kernel(const float* __restrict__ X, int nN) {
    extern __shared__ __half smh[];
    __half* Xs = smh;                               // [128][136]
    __half* Ws = smh + 128 * XS_STRIDE;             // [64][136]
    __half* St = Ws + 64 * WS_STRIDE;               // [128][72]

    const int tid = threadIdx.x;
    const int wid = tid >> 5;
    const int lane = tid & 31;
    const int g = lane >> 2;
    const int tg = lane & 3;
    const int node0 = blockIdx.x * 128;
    const int wrow = wid * 16;

    // Prefetch W_0 into registers (retires under the X-tile load below)
    const uint4* wsrc = (const uint4*)g_Wh;
    uint4 w0 = __ldg(wsrc + tid);
    uint4 w1 = __ldg(wsrc + 256 + tid);
    uint4 w2 = __ldg(wsrc + 512 + tid);
    uint4 w3 = __ldg(wsrc + 768 + tid);

    // Load X tile [128 x 128] fp32 -> fp16 smem
    {
        const float4* X4 = (const float4*)X;
        #pragma unroll 4
        for (int i = tid; i < 4096; i += 256) {
            int row = i >> 5, q = i & 31;
            int gn = node0 + row;
            float4 v = (gn < nN) ? X4[(size_t)gn * 32 + q] : make_float4(0.f, 0.f, 0.f, 0.f);
            __half2 h0 = __floats2half2_rn(v.x, v.y);
            __half2 h1 = __floats2half2_rn(v.z, v.w);
            uint2 packed = make_uint2(*(uint32_t*)&h0, *(uint32_t*)&h1);
            *(uint2*)(Xs + row * XS_STRIDE + q * 4) = packed;
        }
    }

    for (int s = 0; s < NREL; s++) {
        // Store prefetched W_s regs -> smem (i = j*256 + tid; n=i>>4, q=i&15)
        {
            int i0 = tid,        n0 = i0 >> 4, q0 = i0 & 15;
            int i1 = 256 + tid,  n1 = i1 >> 4, q1 = i1 & 15;
            int i2 = 512 + tid,  n2 = i2 >> 4, q2 = i2 & 15;
            int i3 = 768 + tid,  n3 = i3 >> 4, q3 = i3 & 15;
            *(uint4*)(Ws + n0 * WS_STRIDE + q0 * 8) = w0;
            *(uint4*)(Ws + n1 * WS_STRIDE + q1 * 8) = w1;
            *(uint4*)(Ws + n2 * WS_STRIDE + q2 * 8) = w2;
            *(uint4*)(Ws + n3 * WS_STRIDE + q3 * 8) = w3;
        }
        // Prefetch W_{s+1}; LDG hidden under this relation's compute
        if (s < NREL - 1) {
            const uint4* nx = wsrc + (s + 1) * 1024;
            w0 = __ldg(nx + tid);
            w1 = __ldg(nx + 256 + tid);
            w2 = __ldg(nx + 512 + tid);
            w3 = __ldg(nx + 768 + tid);
        }
        __syncthreads();   // Ws visible (s=0: also publishes Xs); St flush of s-1 done

        float d[8][4];
        #pragma unroll
        for (int ni = 0; ni < 8; ni++)
            #pragma unroll
            for (int j = 0; j < 4; j++) d[ni][j] = 0.f;

        #pragma unroll
        for (int ks = 0; ks < 8; ks++) {
            const __half* ar = Xs + (wrow + g) * XS_STRIDE + ks * 16 + tg * 2;
            uint32_t a0 = *(const uint32_t*)(ar);
            uint32_t a1 = *(const uint32_t*)(ar + 8 * XS_STRIDE);
            uint32_t a2 = *(const uint32_t*)(ar + 8);
            uint32_t a3 = *(const uint32_t*)(ar + 8 * XS_STRIDE + 8);
            #pragma unroll
            for (int ni = 0; ni < 8; ni++) {
                const __half* br = Ws + (ni * 8 + g) * WS_STRIDE + ks * 16 + tg * 2;
                uint32_t b0 = *(const uint32_t*)(br);
                uint32_t b1 = *(const uint32_t*)(br + 8);
                mma_f16(d[ni], a0, a1, a2, a3, b0, b1);
            }
        }

        // Stage to smem (conflict-free STS.32)
        {
            __half* s0 = St + (wrow + g) * ST_STRIDE;
            __half* s1 = St + (wrow + 8 + g) * ST_STRIDE;
            #pragma unroll
            for (int ni = 0; ni < 8; ni++) {
                int c = ni * 8 + tg * 2;
                *(__half2*)(s0 + c) = __floats2half2_rn(d[ni][0], d[ni][1]);
                *(__half2*)(s1 + c) = __floats2half2_rn(d[ni][2], d[ni][3]);
            }
        }
        __syncthreads();   // all compute+stage done: St readable, Ws rewritable next iter

        // Coalesced flush (no trailing sync needed: next loop's sync orders St reuse)
        {
            __half* fwbase = g_FWh + (size_t)s * nN * ODIM;
            #pragma unroll
            for (int i = tid; i < 1024; i += 256) {
                int r = i >> 3, q = i & 7;
                int gn = node0 + r;
                if (gn < nN) {
                    uint4 v = *(const uint4*)(St + r * ST_STRIDE + q * 8);
                    *(uint4*)(fwbase + (size_t)gn * ODIM + q * 8) = v;
                }
            }
        }
    }
}

// ---------------------------------------------------------------------------
// Kernel 2: SpMM scatter with L2 residency management:
//   FW gather     -> L2::evict_last  (pin the 102MB FW buffer, ~4x col reuse)
//   idx/val loads -> L2::evict_first (streams must not evict FW)
// 8 threads per edge, 2x red.v4.f32 (atomics measured free; gather-bound)
// ---------------------------------------------------------------------------
__global__ void spmm_kernel(const int* __restrict__ rows, const int* __restrict__ cols,
                            const float* __restrict__ vals, float* __restrict__ out, int E) {
    int t = blockIdx.x * blockDim.x + threadIdx.x;
    int e = t >> 3;
    if (e >= E) return;
    int l = t & 7;

    uint64_t pol_keep, pol_stream;
    asm("createpolicy.fractional.L2::evict_last.b64 %0, 1.0;" : "=l"(pol_keep));
    asm("createpolicy.fractional.L2::evict_first.b64 %0, 1.0;" : "=l"(pol_stream));

    int c, r;
    float v;
    asm("ld.global.nc.L2::cache_hint.b32 %0, [%1], %2;"
        : "=r"(c) : "l"(cols + e), "l"(pol_stream));
    asm("ld.global.nc.L2::cache_hint.b32 %0, [%1], %2;"
        : "=r"(r) : "l"(rows + e), "l"(pol_stream));
    asm("ld.global.nc.L2::cache_hint.b32 %0, [%1], %2;"
        : "=f"(v) : "l"(vals + e), "l"(pol_stream));

    const __half* src = g_FWh + (size_t)c * ODIM + l * 8;
    uint4 p;
    asm("ld.global.nc.L2::cache_hint.v4.b32 {%0,%1,%2,%3}, [%4], %5;"
        : "=r"(p.x), "=r"(p.y), "=r"(p.z), "=r"(p.w)
        : "l"(src), "l"(pol_keep));

    float2 f0 = __half22float2(*(__half2*)&p.x);
    float2 f1 = __half22float2(*(__half2*)&p.y);
    float2 f2 = __half22float2(*(__half2*)&p.z);
    float2 f3 = __half22float2(*(__half2*)&p.w);

    float* dst = out + (size_t)r * ODIM + l * 8;
    asm volatile("red.global.add.v4.f32 [%0], {%1,%2,%3,%4};"
                 :: "l"(dst), "f"(f0.x * v), "f"(f0.y * v), "f"(f1.x * v), "f"(f1.y * v) : "memory");
    asm volatile("red.global.add.v4.f32 [%0], {%1,%2,%3,%4};"
                 :: "l"(dst + 4), "f"(f2.x * v), "f"(f2.y * v), "f"(f3.x * v), "f"(f3.y * v) : "memory");
}

// ---------------------------------------------------------------------------
// Kernel 3: out = relu(out + bias)
// ---------------------------------------------------------------------------
__global__ void bias_relu_kernel(float* __restrict__ out, const float* __restrict__ bias, int nN) {
    int idx = blockIdx.x * blockDim.x + threadIdx.x;
    int total = nN * 16;
    if (idx >= total) return;
    float4 v = ((float4*)out)[idx];
    int og = idx & 15;
    float4 bb = __ldg((const float4*)bias + og);
    v.x = fmaxf(v.x + bb.x, 0.f);
    v.y = fmaxf(v.y + bb.y, 0.f);
    v.z = fmaxf(v.z + bb.z, 0.f);
    v.w = fmaxf(v.w + bb.w, 0.f);
    ((float4*)out)[idx] = v;
}

// ---------------------------------------------------------------------------
extern "C" void kernel_launch(void* const* d_in, const int* in_sizes, int n_in,
                              void* d_out, int out_size) {
    const float* X     = (const float*)d_in[0];   // [N, 128]
    const int*   rows  = (const int*)  d_in[1];   // [E]
    const int*   cols  = (const int*)  d_in[2];   // [E]
    const float* vals  = (const float*)d_in[3];   // [E]
    const float* bases = (const float*)d_in[4];   // [4, 128, 64]
    const float* comp  = (const float*)d_in[5];   // [8, 4]
    const float* bias  = (const float*)d_in[6];   // [64]
    float* out = (float*)d_out;                   // [N, 64]

    int nN = in_sizes[0] / FDIM;
    int E  = in_sizes[1];

    cudaFuncSetAttribute(gemm_fw_kernel, cudaFuncAttributeMaxDynamicSharedMemorySize, SMEM_GEMM);

    cudaMemsetAsync(out, 0, (size_t)nN * ODIM * sizeof(float));

    wcomb_kernel<<<(NREL * FDIM * ODIM + 255) / 256, 256>>>(bases, comp);

    int gblocks = (nN + 127) / 128;
    gemm_fw_kernel<<<gblocks, 256, SMEM_GEMM>>>(X, nN);

    long long spthreads = (long long)E * 8;
    spmm_kernel<<<(int)((spthreads + 255) / 256), 256>>>(rows, cols, vals, out, E);

    bias_relu_kernel<<<(nN * 16 + 255) / 256, 256>>>(out, bias, nN);
}